// round 11
// baseline (speedup 1.0000x reference)
#include <cuda_runtime.h>
#include <cstdint>

// Local2d as 1024 GEMMs C[o,b] = sum_k W[o,k]*P[b,k], M=128, N=64, K=576.
// tf32 mma.sync.m16n8k8 (compute_103-safe).
// Round 10: 256 thr / 8 warps; weight via 256-bit LDG with L2::evict_first
// (legal form), x via plain __ldg (protected in L2 by the evict_first stream);
// vectorized transpose+bias epilogue kernel.

#define KTOT  576
#define KC    32
#define NCH   18
#define APAD  36
#define A_BUF_WORDS (128 * APAD)
#define B_BUF_WORDS 2048
#define AOFF(b) ((b) * A_BUF_WORDS)
#define BOFF(b) (2 * A_BUF_WORDS + (b) * B_BUF_WORDS)
#define SMEM_BYTES ((2 * A_BUF_WORDS + 2 * B_BUF_WORDS) * 4)
#define W_STRIDE_O (1024 * KTOT)

__device__ float g_scratch[1024 * 128 * 64];   // [loc][o][b]

__device__ __forceinline__ uint32_t f2tf32(float f) {
    uint32_t u;
    asm("cvt.rna.tf32.f32 %0, %1;" : "=r"(u) : "f"(f));
    return u;
}
// 256-bit streaming load with evict_first (the only scalar-hint form ptxas takes)
__device__ __forceinline__ void ldg_ef8(const float* p, float (&v)[8]) {
    asm("ld.global.nc.L2::evict_first.v8.b32 {%0,%1,%2,%3,%4,%5,%6,%7}, [%8];"
        : "=f"(v[0]), "=f"(v[1]), "=f"(v[2]), "=f"(v[3]),
          "=f"(v[4]), "=f"(v[5]), "=f"(v[6]), "=f"(v[7]) : "l"(p));
}
__device__ __forceinline__ void mma_tf32(float* d, const uint32_t* a, uint32_t b0, uint32_t b1) {
    asm volatile(
        "mma.sync.aligned.m16n8k8.row.col.f32.tf32.tf32.f32 "
        "{%0,%1,%2,%3}, {%4,%5,%6,%7}, {%8,%9}, {%0,%1,%2,%3};"
        : "+f"(d[0]), "+f"(d[1]), "+f"(d[2]), "+f"(d[3])
        : "r"(a[0]), "r"(a[1]), "r"(a[2]), "r"(a[3]), "r"(b0), "r"(b1));
}

// ---- kernel 1: per-location GEMM, 256 threads ----

__device__ __forceinline__ void prefetch(int c, int loc, int h, int w, int tid,
                                         const float* __restrict__ weight,
                                         const float* __restrict__ x,
                                         float (&wr)[2][8], float (&pr)[8]) {
    const int k0 = c * KC;
    const float* wg = weight + (size_t)loc * KTOT;
#pragma unroll
    for (int j = 0; j < 2; j++) {              // W: 128o x 32k, 2 x LDG.256/thread
        int idx = j * 256 + tid;
        int o   = idx >> 2;
        int oct = idx & 3;
        ldg_ef8(wg + (size_t)o * W_STRIDE_O + k0 + oct * 8, wr[j]);
    }
    const int kkl = tid & 31;
    const int kg  = k0 + kkl;
    const int ci  = kg / 9;
    const int r   = kg - ci * 9;
    const int dh  = r / 3;
    const int dw  = r - dh * 3;
    const int hh  = h - 1 + dh;
    const int ww  = w - 1 + dw;
    const bool in = ((unsigned)hh < 32u) && ((unsigned)ww < 32u);
    const int w5  = tid >> 5;
#pragma unroll
    for (int j = 0; j < 8; j++) {              // P: 64b x 32k gather (L2-resident x)
        int b = j * 8 + w5;
        pr[j] = in ? __ldg(x + (((b << 6) + ci) << 10) + (hh << 5) + ww) : 0.f;
    }
}

__device__ __forceinline__ void store_chunk(uint32_t* sm, int buf, int tid,
                                            const float (&wr)[2][8], const float (&pr)[8]) {
#pragma unroll
    for (int j = 0; j < 2; j++) {
        int idx = j * 256 + tid;
        int o   = idx >> 2;
        int oct = idx & 3;
        uint4 v0, v1;
        v0.x = f2tf32(wr[j][0]); v0.y = f2tf32(wr[j][1]);
        v0.z = f2tf32(wr[j][2]); v0.w = f2tf32(wr[j][3]);
        v1.x = f2tf32(wr[j][4]); v1.y = f2tf32(wr[j][5]);
        v1.z = f2tf32(wr[j][6]); v1.w = f2tf32(wr[j][7]);
        uint32_t* dst = sm + AOFF(buf) + o * APAD + oct * 8;
        *(uint4*)dst       = v0;               // conflict-free per quarter-warp phase
        *(uint4*)(dst + 4) = v1;
    }
    const int kk = tid & 31;
    const int ks = kk >> 3, klo = kk & 7;
    const int t2 = klo & 3, hf = klo >> 2;
    const int g2 = tid >> 5;                   // = b & 7
#pragma unroll
    for (int j = 0; j < 8; j++) {              // nt = j
        int word = (ks * 512 + j * 64 + (g2 * 4 + t2) * 2 + hf) ^ (ks << 3);
        sm[BOFF(buf) + word] = f2tf32(pr[j]);
    }
}

__global__ __launch_bounds__(256, 2)
void local2d_mma_kernel(const float* __restrict__ x,
                        const float* __restrict__ weight)
{
    extern __shared__ uint32_t sm[];
    const int tid  = threadIdx.x;
    const int warp = tid >> 5;
    const int lane = tid & 31;
    const int g    = lane >> 2;
    const int t    = lane & 3;
    const int wo   = warp * 16;                // warp M base (8 warps x 16)
    const int loc  = blockIdx.x;
    const int h    = loc >> 5, w = loc & 31;

    float d[8][4];
#pragma unroll
    for (int j = 0; j < 8; j++)
#pragma unroll
        for (int e = 0; e < 4; e++) d[j][e] = 0.f;

    float wr[2][8];
    float pr[8];

    prefetch(0, loc, h, w, tid, weight, x, wr, pr);
    store_chunk(sm, 0, tid, wr, pr);

#pragma unroll 1
    for (int c = 0; c < NCH; c++) {
        if (c + 1 < NCH) prefetch(c + 1, loc, h, w, tid, weight, x, wr, pr);
        __syncthreads();

        const uint32_t* Ab = sm + AOFF(c & 1);
        const uint32_t* Bb = sm + BOFF(c & 1);
        const uint32_t* Ar = Ab + (wo + g) * APAD;

#pragma unroll
        for (int ks = 0; ks < 4; ks++) {
            uint32_t a[4];
            a[0] = Ar[ks * 8 + t];
            a[1] = Ar[8 * APAD + ks * 8 + t];
            a[2] = Ar[ks * 8 + t + 4];
            a[3] = Ar[8 * APAD + ks * 8 + t + 4];
#pragma unroll
            for (int nt = 0; nt < 8; nt++) {
                int word = (ks * 512 + nt * 64 + lane * 2) ^ (ks << 3);
                uint2 bb = *(const uint2*)(Bb + word);
                mma_tf32(d[nt], a, bb.x, bb.y);
            }
        }

        if (c + 1 < NCH) store_chunk(sm, (c + 1) & 1, tid, wr, pr);
    }

    // epilogue -> scratch[loc][o][b], coalesced float2 runs
    float* sc = g_scratch + (size_t)loc * (128 * 64);
#pragma unroll
    for (int ab = 0; ab < 2; ab++) {
        int r = wo + ab * 8 + g;
#pragma unroll
        for (int nt = 0; nt < 8; nt++) {
            float2 v = make_float2(d[nt][ab * 2 + 0], d[nt][ab * 2 + 1]);
            *(float2*)(sc + r * 64 + nt * 8 + 2 * t) = v;
        }
    }
}

// ---- kernel 2: scratch[loc][o][b] -> out[b][o][loc] + bias, vectorized ----

__global__ __launch_bounds__(128)
void transpose_bias_kernel(const float* __restrict__ bias,
                           float* __restrict__ out)
{
    __shared__ float s[64][33];
    __shared__ float sbias[32];
    const int loc0 = blockIdx.x * 32;
    const int o    = blockIdx.y;
    const int tid  = threadIdx.x;

    if (tid < 32) sbias[tid] = bias[(o << 10) + loc0 + tid];

    {   // load: float4 over b, transpose-scatter into s[b][loc]
        const int f  = tid & 15;       // b quad
        const int r0 = tid >> 4;       // 0..7
        const float* src = g_scratch + ((size_t)(loc0 + r0) * 128 + o) * 64 + f * 4;
#pragma unroll
        for (int i = 0; i < 4; i++) {
            int row = i * 8 + r0;
            float4 v = *(const float4*)(src + (size_t)i * 8 * 128 * 64);
            s[f * 4 + 0][row] = v.x;
            s[f * 4 + 1][row] = v.y;
            s[f * 4 + 2][row] = v.z;
            s[f * 4 + 3][row] = v.w;
        }
    }
    __syncthreads();

    {   // store: gather loc-quads, add bias, STG.128
        const int b    = tid >> 1;
        const int half = tid & 1;
        float* dst = out + ((size_t)(b * 128 + o) << 10) + loc0;
#pragma unroll
        for (int i = 0; i < 4; i++) {
            int lq = half * 16 + i * 4;
            float4 u;
            u.x = s[b][lq + 0] + sbias[lq + 0];
            u.y = s[b][lq + 1] + sbias[lq + 1];
            u.z = s[b][lq + 2] + sbias[lq + 2];
            u.w = s[b][lq + 3] + sbias[lq + 3];
            *(float4*)(dst + lq) = u;
        }
    }
}

extern "C" void kernel_launch(void* const* d_in, const int* in_sizes, int n_in,
                              void* d_out, int out_size) {
    const float* x      = (const float*)d_in[0];
    const float* weight = (const float*)d_in[1];
    const float* bias   = (const float*)d_in[2];
    float* out = (float*)d_out;

    cudaFuncSetAttribute(local2d_mma_kernel,
                         cudaFuncAttributeMaxDynamicSharedMemorySize, SMEM_BYTES);
    local2d_mma_kernel<<<1024, 256, SMEM_BYTES>>>(x, weight);
    transpose_bias_kernel<<<dim3(32, 128), 128>>>(bias, out);
}

// round 13
// speedup vs baseline: 1.0628x; 1.0628x over previous
#include <cuda_runtime.h>
#include <cstdint>

// Local2d as 1024 GEMMs C[o,b] = sum_k W[o,k]*P[b,k], M=128, N=64, K=576.
// tf32 mma.sync.m16n8k8. Round 12: round-7 shape (128 thr, warp tile 32x64)
// + 3-stage cp.async pipeline for the weight stream (global->smem direct),
// A converted to tf32 after LDS (rna, full accuracy). K2 = round-7 version.

#define KTOT  576
#define KC    32
#define NCH   18
#define APAD  36
#define A_WORDS (128 * APAD)              // 4608
#define B_WORDS 2048
#define STAGE_WORDS (A_WORDS + B_WORDS)   // 6656
#define AOFF(s) ((s) * STAGE_WORDS)
#define BOFF(s) ((s) * STAGE_WORDS + A_WORDS)
#define SMEM_BYTES (3 * STAGE_WORDS * 4)  // 79872
#define W_STRIDE_O (1024 * KTOT)

__device__ float g_scratch[1024 * 128 * 64];   // [loc][o][b] (32MB, L2-resident)

__device__ __forceinline__ uint32_t f2tf32(float f) {
    uint32_t u;
    asm("cvt.rna.tf32.f32 %0, %1;" : "=r"(u) : "f"(f));
    return u;
}
__device__ __forceinline__ uint32_t smem_u32(const void* p) {
    uint32_t a;
    asm("{ .reg .u64 t; cvta.to.shared.u64 t, %1; cvt.u32.u64 %0, t; }" : "=r"(a) : "l"(p));
    return a;
}
__device__ __forceinline__ void cp16(uint32_t dst, const float* src) {
    asm volatile("cp.async.cg.shared.global [%0], [%1], 16;" :: "r"(dst), "l"(src));
}
#define CP_COMMIT() asm volatile("cp.async.commit_group;" ::: "memory")
#define CP_WAIT(n)  asm volatile("cp.async.wait_group %0;" :: "n"(n) : "memory")

__device__ __forceinline__ void mma_tf32(float* d, const uint32_t* a, uint32_t b0, uint32_t b1) {
    asm volatile(
        "mma.sync.aligned.m16n8k8.row.col.f32.tf32.tf32.f32 "
        "{%0,%1,%2,%3}, {%4,%5,%6,%7}, {%8,%9}, {%0,%1,%2,%3};"
        : "+f"(d[0]), "+f"(d[1]), "+f"(d[2]), "+f"(d[3])
        : "r"(a[0]), "r"(a[1]), "r"(a[2]), "r"(a[3]), "r"(b0), "r"(b1));
}

__global__ __launch_bounds__(128, 2)
void local2d_mma_kernel(const float* __restrict__ x,
                        const float* __restrict__ weight)
{
    extern __shared__ uint32_t sm[];
    const uint32_t sbase = smem_u32(sm);
    const int tid  = threadIdx.x;
    const int warp = tid >> 5;
    const int lane = tid & 31;
    const int g    = lane >> 2;
    const int t    = lane & 3;
    const int wo   = warp * 32;               // warp M base (4 warps x 32)
    const int loc  = blockIdx.x;
    const int h    = loc >> 5, w = loc & 31;

    // ---- per-thread invariant addressing ----
    // W via cp.async: thread covers o = o0+16j (j=0..7), fixed k-quad q.
    const int o0 = tid >> 3;
    const int q  = tid & 7;
    const float* wsrc0 = weight + (size_t)loc * KTOT + (size_t)o0 * W_STRIDE_O + q * 4;
    const uint32_t adst0 = o0 * 144 + q * 16;   // bytes within A stage
    // P gather: fixed k within chunk, b = 4j + (tid>>5)
    const int kkl = tid & 31;
    const int ci0 = kkl / 9;                    // only chunk-dependent parts vary
    // B store fragment constants
    const int ks_s = kkl >> 3, klo = kkl & 7;
    const int t2 = klo & 3, hf = klo >> 2;

    float d[2][8][4];
#pragma unroll
    for (int i = 0; i < 2; i++)
#pragma unroll
        for (int j = 0; j < 8; j++)
#pragma unroll
            for (int e = 0; e < 4; e++) d[i][j][e] = 0.f;

    float pr[16];

    // ---- helpers as lambdas ----
    auto issue_W = [&](int c, int stage) {
        const float* src = wsrc0 + c * KC;
        uint32_t dst = sbase + AOFF(stage) * 4 + adst0;
#pragma unroll
        for (int j = 0; j < 8; j++)
            cp16(dst + j * 2304, src + (size_t)j * 16 * W_STRIDE_O);
        CP_COMMIT();
    };
    auto fetch_P = [&](int c) {
        const int kg = c * KC + kkl;
        const int ci = kg / 9;
        const int r  = kg - ci * 9;
        const int dh = r / 3;
        const int dw = r - dh * 3;
        const int hh = h - 1 + dh;
        const int ww = w - 1 + dw;
        const bool in = ((unsigned)hh < 32u) && ((unsigned)ww < 32u);
        const int w5 = tid >> 5;
#pragma unroll
        for (int j = 0; j < 16; j++) {
            int b = j * 4 + w5;
            pr[j] = in ? __ldg(x + (((b << 6) + ci) << 10) + (hh << 5) + ww) : 0.f;
        }
    };
    auto store_P = [&](int stage) {
        uint32_t* Bb = sm + BOFF(stage);
        const int w5 = tid >> 5;
#pragma unroll
        for (int j = 0; j < 16; j++) {
            int b  = j * 4 + w5;
            int nt = b >> 3, g2 = b & 7;
            int word = (ks_s * 512 + nt * 64 + (g2 * 4 + t2) * 2 + hf) ^ (ks_s << 3);
            Bb[word] = f2tf32(pr[j]);
        }
    };

    // ---- prologue: stages 0,1 in flight ----
    issue_W(0, 0);
    issue_W(1, 1);
    fetch_P(0); store_P(0);
    fetch_P(1); store_P(1);

#pragma unroll 1
    for (int c = 0; c < NCH; c++) {
        if (c < NCH - 1) CP_WAIT(1); else CP_WAIT(0);   // chunk c's W complete
        __syncthreads();                                 // publish W+P of stage c%3

        if (c + 2 < NCH) {                               // refill stage (c+2)%3
            issue_W(c + 2, (c + 2) % 3);                 // safe: readers (chunk c-1) done
            fetch_P(c + 2);
        }

        const uint32_t* Ab = sm + AOFF(c % 3);
        const uint32_t* Bb = sm + BOFF(c % 3);
        const float*    Ar = (const float*)Ab + (wo + g) * APAD;

#pragma unroll
        for (int ks = 0; ks < 4; ks++) {
            uint32_t a[2][4];
#pragma unroll
            for (int mt = 0; mt < 2; mt++) {
                const float* ap = Ar + mt * (16 * APAD) + ks * 8 + t;
                a[mt][0] = f2tf32(ap[0]);
                a[mt][1] = f2tf32(ap[8 * APAD]);
                a[mt][2] = f2tf32(ap[4]);
                a[mt][3] = f2tf32(ap[8 * APAD + 4]);
            }
#pragma unroll
            for (int nt = 0; nt < 8; nt++) {
                int word = (ks * 512 + nt * 64 + lane * 2) ^ (ks << 3);
                uint2 bb = *(const uint2*)(Bb + word);
                mma_tf32(d[0][nt], a[0], bb.x, bb.y);
                mma_tf32(d[1][nt], a[1], bb.x, bb.y);
            }
        }

        if (c + 2 < NCH) store_P((c + 2) % 3);           // safe post-MMA (readers done)
    }

    // ---- epilogue -> scratch[loc][o][b], coalesced float2 runs ----
    float* sc = g_scratch + (size_t)loc * (128 * 64);
#pragma unroll
    for (int mt = 0; mt < 2; mt++)
#pragma unroll
        for (int ab = 0; ab < 2; ab++) {
            int r = wo + mt * 16 + ab * 8 + g;
#pragma unroll
            for (int nt = 0; nt < 8; nt++) {
                float2 v = make_float2(d[mt][nt][ab * 2 + 0], d[mt][nt][ab * 2 + 1]);
                *(float2*)(sc + r * 64 + nt * 8 + 2 * t) = v;
            }
        }
}

// ---- kernel 2 (round-7 version): scratch[loc][o][b] -> out[b][o][loc] + bias ----
__global__ __launch_bounds__(256)
void transpose_bias_kernel(const float* __restrict__ bias,
                           float* __restrict__ out)
{
    __shared__ float s2[32][65];
    const int loc0 = blockIdx.x * 32;
    const int o    = blockIdx.y;
    const int tid  = threadIdx.x;

    {   // load: rows = loc, cols = b (coalesced 128B per half-row)
        const int c = tid & 63, r0 = tid >> 6;
#pragma unroll
        for (int i = 0; i < 8; i++) {
            int r = i * 4 + r0;
            s2[r][c] = g_scratch[((size_t)(loc0 + r) * 128 + o) * 64 + c];
        }
    }
    __syncthreads();

    const int lc = tid & 31;
    const int b0 = tid >> 5;
    const float bv = bias[(o << 10) + loc0 + lc];
#pragma unroll
    for (int i = 0; i < 8; i++) {
        int b = i * 8 + b0;
        out[((size_t)(b * 128 + o) << 10) + loc0 + lc] = s2[lc][b] + bv;
    }
}

extern "C" void kernel_launch(void* const* d_in, const int* in_sizes, int n_in,
                              void* d_out, int out_size) {
    const float* x      = (const float*)d_in[0];
    const float* weight = (const float*)d_in[1];
    const float* bias   = (const float*)d_in[2];
    float* out = (float*)d_out;

    cudaFuncSetAttribute(local2d_mma_kernel,
                         cudaFuncAttributeMaxDynamicSharedMemorySize, SMEM_BYTES);
    local2d_mma_kernel<<<1024, 128, SMEM_BYTES>>>(x, weight);
    transpose_bias_kernel<<<dim3(32, 128), 256>>>(bias, out);
}